// round 1
// baseline (speedup 1.0000x reference)
#include <cuda_runtime.h>

// ---------------------------------------------------------------------------
// GAT (2-layer GATConv), N=50000 nodes, E=850000 edges (incl self-loops),
// F_IN=128, H=4, D=32. Strategy:
//   1. counting-sort edges by dst (hist -> scan -> scatter) once, reuse twice
//   2. per layer: GEMM feat = X@W with fused el/er epilogue
//   3. per layer: warp-per-dst-node kernel: edge scores -> softmax -> weighted
//      float4 gather of feat[src] accumulated in registers (no atomics)
// ---------------------------------------------------------------------------

#define FULL 0xffffffffu

constexpr int NN = 50000;
constexpr int EE = 850000;
constexpr int FH = 128;   // H*D
constexpr int HH = 4;
constexpr int DD = 32;
constexpr int SCAN_B = 1024;
constexpr int SCAN_NB = (NN + SCAN_B - 1) / SCAN_B;   // 49

// scratch (device globals; no allocation allowed)
__device__ float g_feat[NN * FH];     // per-layer projected features
__device__ float g_hid[NN * FH];      // layer-1 output / layer-2 input
__device__ float g_el[NN * HH];
__device__ float g_er[NN * HH];
__device__ float g_esc[EE * HH];      // edge scores / exp values (sorted order)
__device__ int   g_counts[NN];
__device__ int   g_cursor[NN];
__device__ int   g_off[NN + 1];
__device__ int   g_excl[NN];
__device__ int   g_bsum[64];
__device__ int   g_bsumoff[64];
__device__ int   g_ssrc[EE];          // src node of each sorted edge

// ---------------------------------------------------------------------------
__global__ void k_init() {
    int i = blockIdx.x * blockDim.x + threadIdx.x;
    if (i < NN) { g_counts[i] = 0; g_cursor[i] = 0; }
}

__global__ void k_hist(const int* __restrict__ dst) {
    int i = blockIdx.x * blockDim.x + threadIdx.x;
    if (i < EE) atomicAdd(&g_counts[dst[i]], 1);
}

__global__ void k_scan_blocks() {
    __shared__ int sh[SCAN_B];
    int g = blockIdx.x * SCAN_B + threadIdx.x;
    int v = (g < NN) ? g_counts[g] : 0;
    sh[threadIdx.x] = v;
    __syncthreads();
    for (int o = 1; o < SCAN_B; o <<= 1) {
        int t = (threadIdx.x >= o) ? sh[threadIdx.x - o] : 0;
        __syncthreads();
        sh[threadIdx.x] += t;
        __syncthreads();
    }
    if (g < NN) g_excl[g] = sh[threadIdx.x] - v;   // exclusive
    if (threadIdx.x == SCAN_B - 1) g_bsum[blockIdx.x] = sh[SCAN_B - 1];
}

__global__ void k_scan_bsums() {
    __shared__ int sh[64];
    int t = threadIdx.x;
    int v = (t < SCAN_NB) ? g_bsum[t] : 0;
    sh[t] = v;
    __syncthreads();
    for (int o = 1; o < 64; o <<= 1) {
        int u = (t >= o) ? sh[t - o] : 0;
        __syncthreads();
        sh[t] += u;
        __syncthreads();
    }
    if (t < SCAN_NB) g_bsumoff[t] = sh[t] - v;    // exclusive
}

__global__ void k_scan_add() {
    int g = blockIdx.x * SCAN_B + threadIdx.x;
    if (g < NN) g_off[g] = g_excl[g] + g_bsumoff[blockIdx.x];
    if (g == 0) g_off[NN] = EE;
}

__global__ void k_scatter(const int* __restrict__ src, const int* __restrict__ dst) {
    int i = blockIdx.x * blockDim.x + threadIdx.x;
    if (i < EE) {
        int v = dst[i];
        int pos = g_off[v] + atomicAdd(&g_cursor[v], 1);
        g_ssrc[pos] = src[i];
    }
}

// ---------------------------------------------------------------------------
// GEMM: feat[N,128] = X[N,128] @ W[128,128], fused el/er projections.
// 256 threads/block, 64 rows/block, warp computes 8 rows x 128 cols (4/lane).
// ---------------------------------------------------------------------------
__global__ void k_gemm(const float* __restrict__ X, const float* __restrict__ W,
                       const float* __restrict__ al, const float* __restrict__ ar) {
    constexpr int GR = 64, KC = 32;
    __shared__ float4 Wsh[KC][32];    // [k][col/4]
    __shared__ float  Xsh[GR][KC];

    int tid = threadIdx.x, lane = tid & 31, warp = tid >> 5;
    int row0 = blockIdx.x * GR;

    float acc[8][4];
#pragma unroll
    for (int r = 0; r < 8; r++)
#pragma unroll
        for (int j = 0; j < 4; j++) acc[r][j] = 0.f;

    const float4* W4 = reinterpret_cast<const float4*>(W);

    for (int kc = 0; kc < FH; kc += KC) {
        for (int i = tid; i < KC * 32; i += 256) {
            int kk = i >> 5, cc = i & 31;
            Wsh[kk][cc] = W4[(kc + kk) * 32 + cc];
        }
        for (int i = tid; i < GR * KC; i += 256) {
            int r = i / KC, k = i % KC;
            int row = row0 + r;
            Xsh[r][k] = (row < NN) ? X[row * FH + kc + k] : 0.f;
        }
        __syncthreads();
#pragma unroll 8
        for (int k = 0; k < KC; k++) {
            float4 w = Wsh[k][lane];
#pragma unroll
            for (int r = 0; r < 8; r++) {
                float a = Xsh[warp * 8 + r][k];
                acc[r][0] = fmaf(a, w.x, acc[r][0]);
                acc[r][1] = fmaf(a, w.y, acc[r][1]);
                acc[r][2] = fmaf(a, w.z, acc[r][2]);
                acc[r][3] = fmaf(a, w.w, acc[r][3]);
            }
        }
        __syncthreads();
    }

    // epilogue: store feat + fused el/er (segmented 8-lane reduction)
    int h = lane >> 3, d0 = (lane & 7) * 4;
    float4 alv = reinterpret_cast<const float4*>(al)[(h * DD + d0) >> 2];
    float4 arv = reinterpret_cast<const float4*>(ar)[(h * DD + d0) >> 2];
    float4* feat4 = reinterpret_cast<float4*>(g_feat);

#pragma unroll
    for (int r = 0; r < 8; r++) {
        int row = row0 + warp * 8 + r;
        if (row < NN) {
            feat4[row * 32 + lane] = make_float4(acc[r][0], acc[r][1], acc[r][2], acc[r][3]);
        }
        float elp = acc[r][0] * alv.x + acc[r][1] * alv.y + acc[r][2] * alv.z + acc[r][3] * alv.w;
        float erp = acc[r][0] * arv.x + acc[r][1] * arv.y + acc[r][2] * arv.z + acc[r][3] * arv.w;
#pragma unroll
        for (int o = 4; o; o >>= 1) {
            elp += __shfl_xor_sync(FULL, elp, o);
            erp += __shfl_xor_sync(FULL, erp, o);
        }
        if (row < NN && (lane & 7) == 0) {
            g_el[row * HH + h] = elp;
            g_er[row * HH + h] = erp;
        }
    }
}

// ---------------------------------------------------------------------------
// Node kernel: one warp per dst node.
//   pass1: e = leaky(el[src]+er[v], 0.2), store, track per-head max
//   pass2: ex = exp(e - max), store, sum
//   pass3: acc += (ex/sum) * feat[src]   (float4/lane, 4-way edge unroll)
// ---------------------------------------------------------------------------
__device__ __forceinline__ float4 wred_max4(float4 v) {
#pragma unroll
    for (int o = 16; o; o >>= 1) {
        v.x = fmaxf(v.x, __shfl_xor_sync(FULL, v.x, o));
        v.y = fmaxf(v.y, __shfl_xor_sync(FULL, v.y, o));
        v.z = fmaxf(v.z, __shfl_xor_sync(FULL, v.z, o));
        v.w = fmaxf(v.w, __shfl_xor_sync(FULL, v.w, o));
    }
    return v;
}
__device__ __forceinline__ float4 wred_sum4(float4 v) {
#pragma unroll
    for (int o = 16; o; o >>= 1) {
        v.x += __shfl_xor_sync(FULL, v.x, o);
        v.y += __shfl_xor_sync(FULL, v.y, o);
        v.z += __shfl_xor_sync(FULL, v.z, o);
        v.w += __shfl_xor_sync(FULL, v.w, o);
    }
    return v;
}
__device__ __forceinline__ float lk(float x, float s) { return x > 0.f ? x : x * s; }

__global__ void k_node(const float* __restrict__ bias, float* __restrict__ out,
                       float act_slope, int apply_act) {
    int wg = (blockIdx.x * blockDim.x + threadIdx.x) >> 5;
    int lane = threadIdx.x & 31;
    if (wg >= NN) return;
    int v = wg;
    int start = g_off[v], end = g_off[v + 1];

    const float4* feat4 = reinterpret_cast<const float4*>(g_feat);
    const float4* el4 = reinterpret_cast<const float4*>(g_el);
    float4* esc4 = reinterpret_cast<float4*>(g_esc);
    const float* escf = g_esc;

    float4 erv = reinterpret_cast<const float4*>(g_er)[v];

    // pass1: scores + max
    float4 mx = make_float4(-1e30f, -1e30f, -1e30f, -1e30f);
    for (int p = start + lane; p < end; p += 32) {
        int s = g_ssrc[p];
        float4 e = el4[s];
        e.x = lk(e.x + erv.x, 0.2f);
        e.y = lk(e.y + erv.y, 0.2f);
        e.z = lk(e.z + erv.z, 0.2f);
        e.w = lk(e.w + erv.w, 0.2f);
        esc4[p] = e;
        mx.x = fmaxf(mx.x, e.x); mx.y = fmaxf(mx.y, e.y);
        mx.z = fmaxf(mx.z, e.z); mx.w = fmaxf(mx.w, e.w);
    }
    mx = wred_max4(mx);

    // pass2: exp + sum
    float4 sm = make_float4(0.f, 0.f, 0.f, 0.f);
    for (int p = start + lane; p < end; p += 32) {
        float4 e = esc4[p];
        e.x = __expf(e.x - mx.x);
        e.y = __expf(e.y - mx.y);
        e.z = __expf(e.z - mx.z);
        e.w = __expf(e.w - mx.w);
        esc4[p] = e;
        sm.x += e.x; sm.y += e.y; sm.z += e.z; sm.w += e.w;
    }
    sm = wred_sum4(sm);

    int h = lane >> 3;
    float shd = (h == 0) ? sm.x : (h == 1) ? sm.y : (h == 2) ? sm.z : sm.w;
    float inv = 1.f / shd;

    // pass3: weighted gather, 4-way unroll over edges
    float4 a0 = make_float4(0, 0, 0, 0), a1 = a0, a2 = a0, a3 = a0;
    int p = start;
#define STEP(PP, ACC)                                           \
    {                                                           \
        int s_ = g_ssrc[PP];                                    \
        float a_ = escf[(PP) * 4 + h] * inv;                    \
        float4 f_ = feat4[s_ * 32 + lane];                      \
        ACC.x = fmaf(a_, f_.x, ACC.x);                          \
        ACC.y = fmaf(a_, f_.y, ACC.y);                          \
        ACC.z = fmaf(a_, f_.z, ACC.z);                          \
        ACC.w = fmaf(a_, f_.w, ACC.w);                          \
    }
    for (; p + 4 <= end; p += 4) {
        STEP(p + 0, a0); STEP(p + 1, a1); STEP(p + 2, a2); STEP(p + 3, a3);
    }
    for (; p < end; ++p) STEP(p, a0);
#undef STEP
    float4 acc;
    acc.x = (a0.x + a1.x) + (a2.x + a3.x);
    acc.y = (a0.y + a1.y) + (a2.y + a3.y);
    acc.z = (a0.z + a1.z) + (a2.z + a3.z);
    acc.w = (a0.w + a1.w) + (a2.w + a3.w);

    float4 b = reinterpret_cast<const float4*>(bias)[lane];
    acc.x += b.x; acc.y += b.y; acc.z += b.z; acc.w += b.w;
    if (apply_act) {
        acc.x = lk(acc.x, act_slope);
        acc.y = lk(acc.y, act_slope);
        acc.z = lk(acc.z, act_slope);
        acc.w = lk(acc.w, act_slope);
    }
    reinterpret_cast<float4*>(out)[v * 32 + lane] = acc;
}

// ---------------------------------------------------------------------------
extern "C" void kernel_launch(void* const* d_in, const int* in_sizes, int n_in,
                              void* d_out, int out_size) {
    const float* x   = (const float*)d_in[0];
    const int*   src = (const int*)d_in[1];
    const int*   dst = (const int*)d_in[2];
    const float* W1  = (const float*)d_in[3];
    const float* al1 = (const float*)d_in[4];
    const float* ar1 = (const float*)d_in[5];
    const float* b1  = (const float*)d_in[6];
    const float* W2  = (const float*)d_in[7];
    const float* al2 = (const float*)d_in[8];
    const float* ar2 = (const float*)d_in[9];
    const float* b2  = (const float*)d_in[10];
    float* out = (float*)d_out;

    void* p_hid = nullptr;
    cudaGetSymbolAddress(&p_hid, g_hid);
    float* hid = (float*)p_hid;

    int ethreads = (EE + 255) / 256;
    int nthreads = (NN + 255) / 256;

    // build CSR (dst-sorted edges), reused for both layers
    k_init<<<nthreads, 256>>>();
    k_hist<<<ethreads, 256>>>(dst);
    k_scan_blocks<<<SCAN_NB, SCAN_B>>>();
    k_scan_bsums<<<1, 64>>>();
    k_scan_add<<<SCAN_NB, SCAN_B>>>();
    k_scatter<<<ethreads, 256>>>(src, dst);

    int gemm_blocks = (NN + 63) / 64;
    int node_blocks = (NN + 7) / 8;   // 8 warps/block

    // layer 1
    k_gemm<<<gemm_blocks, 256>>>(x, W1, al1, ar1);
    k_node<<<node_blocks, 256>>>(b1, hid, 0.01f, 1);

    // layer 2
    k_gemm<<<gemm_blocks, 256>>>(hid, W2, al2, ar2);
    k_node<<<node_blocks, 256>>>(b2, out, 0.0f, 0);
}